// round 15
// baseline (speedup 1.0000x reference)
#include <cuda_runtime.h>

#define NS      4
#define NA      8192
#define NC      8
#define THR2    1.21f
#define GRID    32
#define GRIDXY  (GRID * GRID)
#define CELLS   (GRID * GRID * GRID)     // 32768
#define ORIGIN  (-17.632f)
#define INV_H   (1.0f / 1.102f)          // h = 1.102 > 1.1 clash radius
#define NBLK    128                      // build grid: <= #SMs -> co-resident
#define NROWS   (GRID * GRID)            // 1024 cell-rows per sample
#define SBLK    (NS * NROWS)             // 4096 search blocks
#define SMAX    768                      // smem atom capacity (max ~450 real)

// Device-global scratch. Replay invariants: g_counts, g_npc, g_cellCounts,
// g_sd, g_sync* are zero on entry (zero-init at load; consumers re-zero).
__device__ int g_counts[NS * NC * NC];
__device__ int g_npc[NC];
__device__ int g_sd;                     // search blocks done
__device__ int g_sync0, g_sync1, g_sync2;
__device__ int g_partial[NS * 32];       // per-chunk scan partials
__device__ int g_chain[NA];
__device__ __align__(16) int    g_cellCounts[NS][CELLS];
__device__ __align__(16) int    g_cellStarts[NS][CELLS + 4];
__device__ __align__(16) float4 g_pk[NS][NA];   // (x,y,z,q) cell-sorted
__device__ int    g_meta[NS][NA];               // chain of sorted atom

__device__ __forceinline__ int cellco(float v) {
    int c = __float2int_rd((v - ORIGIN) * INV_H);
    return min(GRID - 1, max(0, c));
}

// Grid barrier: valid because all NBLK blocks are co-resident (NBLK <= SMs).
__device__ __forceinline__ void gsync(int* ctr, int* prev) {
    __threadfence();
    __syncthreads();
    if (threadIdx.x == 0) {
        int r = atomicAdd(ctr, 1);
        if (prev && r == NBLK - 1) *prev = 0;
        while (*(volatile int*)ctr < NBLK) __nanosleep(32);
    }
    __syncthreads();
    __threadfence();
}

// ---------------------------------------------------------------------------
// build: hist -> scan -> scatter in ONE persistent kernel (3 barriers).
// Identical to the validated R13 build.
__global__ __launch_bounds__(256) void build_kernel(
    const float* __restrict__ coord,
    const int*   __restrict__ asym,
    const int*   __restrict__ a2t)
{
    __shared__ float s_c[768];
    __shared__ int s_w[8];
    __shared__ int s_off;

    int tid = threadIdx.x;
    int t   = blockIdx.x * 256 + tid;
    int s   = t >> 13;
    int a   = t & (NA - 1);

    {
        const float* cb = coord + (size_t)blockIdx.x * 768;
        s_c[tid]       = cb[tid];
        s_c[tid + 256] = cb[tid + 256];
        s_c[tid + 512] = cb[tid + 512];
    }
    __syncthreads();
    float x = s_c[3 * tid], y = s_c[3 * tid + 1], z = s_c[3 * tid + 2];
    float q = fmaf(x, x, fmaf(y, y, z * z));
    int cell = cellco(x) + GRID * cellco(y) + GRIDXY * cellco(z);
    int rank = atomicAdd(&g_cellCounts[s][cell], 1);
    if (t < NA) {
        int ch = asym[a2t[t]];
        g_chain[t] = ch;
        atomicAdd(&g_npc[ch], 1);
    }

    gsync(&g_sync0, 0);

    int sb = blockIdx.x >> 5;
    int ch = blockIdx.x & 31;
    int base = ch * 1024 + tid * 4;
    int4 v = *(const int4*)(g_cellCounts[sb] + base);
    int sum = v.x + v.y + v.z + v.w;

    int lane = tid & 31, wid = tid >> 5;
    int inc = sum;
#pragma unroll
    for (int d = 1; d < 32; d <<= 1) {
        int u = __shfl_up_sync(0xFFFFFFFF, inc, d);
        if (lane >= d) inc += u;
    }
    if (lane == 31) s_w[wid] = inc;
    __syncthreads();
    if (tid < 8) {
        int wv = s_w[tid];
        int wi = wv;
#pragma unroll
        for (int d = 1; d < 8; d <<= 1) {
            int u = __shfl_up_sync(0xFF, wi, d);
            if (tid >= d) wi += u;
        }
        s_w[tid] = wi - wv;
        if (tid == 7) g_partial[sb * 32 + ch] = wi;
    }
    __syncthreads();
    int run = s_w[wid] + (inc - sum);
    *(int4*)(g_cellCounts[sb] + base) = make_int4(0, 0, 0, 0);

    gsync(&g_sync1, &g_sync0);

    if (tid < 32) {
        int pv = (tid < ch) ? g_partial[sb * 32 + tid] : 0;
#pragma unroll
        for (int d = 16; d > 0; d >>= 1)
            pv += __shfl_down_sync(0xFFFFFFFF, pv, d);
        if (tid == 0) s_off = pv;
    }
    __syncthreads();
    int off = s_off;
    int4 o;
    o.x = run + off;
    o.y = o.x + v.x;
    o.z = o.y + v.y;
    o.w = o.z + v.z;
    *(int4*)(g_cellStarts[sb] + base) = o;
    if (ch == 31 && tid == 255) g_cellStarts[sb][CELLS] = NA;

    gsync(&g_sync2, &g_sync1);

    int pos = g_cellStarts[s][cell] + rank;
    g_pk[s][pos]   = make_float4(x, y, z, q);
    g_meta[s][pos] = g_chain[a];
}

// ---------------------------------------------------------------------------
// search: one block per (sample, cell-row (y,z)). Forward stencil in row form:
//   home row (y,z)            -> smem [0, n0); pairs via j > tid
//   row (y+1, z)              -> contiguous halo span
//   3-row slab (y-1..y+1, z+1) -> contiguous halo span
// Halos are strictly forward rows -> each unordered cross-row pair counted
// once; home pairs once via index order. Pairs >1 cell apart in x are a
// superset rejected by the EXACT distance test (same fp32 fma association as
// the accepted brute-force kernel). All inner-loop reads are LDS broadcasts
// (block-uniform j) — no scattered L1tex gathers.
// Last-arriving block runs the fused finalize and resets replay counters.
// out layout: [ has (256 floats) | details (512 floats, (tot, rel)) ]
__global__ __launch_bounds__(128, 8) void search_kernel(float* __restrict__ out) {
    __shared__ __align__(16) float4 s_pk[SMAX];
    __shared__ int  s_ch[SMAX];
    __shared__ int  scnt[NC * NC];
    __shared__ int  s_last;

    int tid = threadIdx.x;
    if (tid < NC * NC) scnt[tid] = 0;

    int b = blockIdx.x;
    int s = b >> 10;                      // sample
    int r = b & (NROWS - 1);              // row id: y = r&31, z = r>>5
    int y = r & 31, z = r >> 5;

    const int* st = g_cellStarts[s];

    // home row
    int lo0 = st[r << 5];
    int n0  = st[(r << 5) + 32] - lo0;
    // halo 1: row (y+1, z)
    int lo1 = 0, n1 = 0;
    if (y + 1 < GRID) {
        int rb = (r + 1) << 5;
        lo1 = st[rb];
        n1  = st[rb + 32] - lo1;
    }
    // halo 2: 3-row slab (y-1..y+1, z+1), contiguous rows
    int lo2 = 0, n2 = 0;
    if (z + 1 < GRID) {
        int ylo = max(y - 1, 0), yhi = min(y + 1, GRID - 1);
        int ra = (ylo + ((z + 1) << 5)) << 5;
        int rbnd = (yhi + 1 + ((z + 1) << 5)) << 5;
        lo2 = st[ra];
        n2  = st[rbnd] - lo2;
    }
    // clamp to smem capacity (never hit: worst-case ~450 < SMAX)
    n1 = min(n1, SMAX - n0);
    n2 = min(n2, SMAX - n0 - n1);
    int N = n0 + n1 + n2;

    // coalesced stage into smem: home first, then halos
    const float4* pk = g_pk[s];
    const int*    mt = g_meta[s];
    for (int i = tid; i < n0; i += 128) { s_pk[i] = pk[lo0 + i];           s_ch[i] = mt[lo0 + i]; }
    for (int i = tid; i < n1; i += 128) { s_pk[n0 + i] = pk[lo1 + i];      s_ch[n0 + i] = mt[lo1 + i]; }
    for (int i = tid; i < n2; i += 128) { s_pk[n0 + n1 + i] = pk[lo2 + i]; s_ch[n0 + n1 + i] = mt[lo2 + i]; }
    __syncthreads();

    if (tid < n0) {
        float4 p = s_pk[tid];
        int   ci = s_ch[tid];
        float m2x = -2.0f * p.x, m2y = -2.0f * p.y, m2z = -2.0f * p.z;
        float K   = p.w - THR2;
        int bucket = ci * NC;
        // uniform j over the whole list -> LDS broadcast; j>tid guards
        // home once-counting (halo j >= n0 > tid always passes)
#pragma unroll 4
        for (int j = 0; j < N; ++j) {
            float4 a = s_pk[j];
            float d = fmaf(m2z, a.z, fmaf(m2y, a.y, fmaf(m2x, a.x, a.w))) + K;
            if (j > tid && d < 0.0f) {
                int m = s_ch[j];
                if (m != ci) atomicAdd(&scnt[bucket + m], 1);
            }
        }
    }

    __syncthreads();
    if (tid < NC * NC) {
        int v = scnt[tid];
        if (v) atomicAdd(&g_counts[s * NC * NC + tid], v);
    }
    __threadfence();
    __syncthreads();
    if (tid == 0) {
        int rr = atomicAdd(&g_sd, 1);
        s_last = (rr == SBLK - 1);
        if (s_last) { g_sd = 0; g_sync2 = 0; }   // reset replay counters
    }
    __syncthreads();
    if (!s_last) return;

    // ---- fused finalize (first 256... block has 128 threads: 2 items each)
    for (int t2 = tid; t2 < 256; t2 += 128) {
        int fs = t2 >> 6;
        int rr = t2 & 63;
        int a  = rr >> 3;
        int bb = rr & 7;

        int tot_i = 0;
        if (a != bb)
            tot_i = __ldcg(&g_counts[fs * NC * NC + a * NC + bb]) +
                    __ldcg(&g_counts[fs * NC * NC + bb * NC + a]);
        float tot = (float)tot_i;
        float mn  = (float)min(__ldcg(&g_npc[a]), __ldcg(&g_npc[bb]));
        float rel = tot / mn;
        bool  has = (tot > 100.0f) || (rel > 0.5f);

        out[t2]                        = has ? 1.0f : 0.0f;
        out[NS * NC * NC + 2 * t2]     = tot;
        out[NS * NC * NC + 2 * t2 + 1] = rel;
    }
    __syncthreads();                       // all reads done
    for (int t2 = tid; t2 < 256; t2 += 128) g_counts[t2] = 0;
    if (tid < NC) g_npc[tid] = 0;
}

// ---------------------------------------------------------------------------
extern "C" void kernel_launch(void* const* d_in, const int* in_sizes, int n_in,
                              void* d_out, int out_size) {
    const float* coord = (const float*)d_in[0];   // [S, N, 3] f32
    const int*   asym  = (const int*)  d_in[1];   // [N_TOKENS] i32
    const int*   a2t   = (const int*)  d_in[2];   // [N] i32
    float*       out   = (float*)d_out;

    build_kernel <<<NBLK, 256>>>(coord, asym, a2t);
    search_kernel<<<SBLK, 128>>>(out);
}

// round 16
// speedup vs baseline: 1.8889x; 1.8889x over previous
#include <cuda_runtime.h>

#define NS      4
#define NA      8192
#define NC      8
#define THR2    1.21f
#define GRID    32
#define GRIDXY  (GRID * GRID)
#define CELLS   (GRID * GRID * GRID)     // 32768
#define ORIGIN  (-17.632f)
#define INV_H   (1.0f / 1.102f)          // h = 1.102 > 1.1 clash radius
#define NBLK    128                      // build grid: <= #SMs -> co-resident
#define SBLK    (5 * 128)                // search blocks (5 segments)

// Device-global scratch. Replay invariants: g_counts, g_npc, g_cellCounts,
// g_sd, g_sync* are zero on entry (zero-init at load; consumers re-zero).
__device__ int g_counts[NS * NC * NC];
__device__ int g_npc[NC];
__device__ int g_sd;                     // search blocks done
__device__ int g_sync0, g_sync1, g_sync2;
__device__ int g_partial[NS * 32];       // per-chunk scan partials
__device__ int g_chain[NA];
__device__ __align__(16) int    g_cellCounts[NS][CELLS];
__device__ __align__(16) int    g_cellStarts[NS][CELLS + 4];
__device__ __align__(16) float4 g_pk[NS][NA];   // (x,y,z,q) cell-sorted
__device__ int    g_meta[NS][NA];               // chain of sorted atom

__device__ __forceinline__ int cellco(float v) {
    int c = __float2int_rd((v - ORIGIN) * INV_H);
    return min(GRID - 1, max(0, c));
}

// Grid barrier: valid because all NBLK blocks are co-resident (NBLK <= SMs).
// nanosleep poll (measured cheaper than pure spin). prev (if non-null) is
// reset by the LAST arriver — every block already passed prev's poll.
__device__ __forceinline__ void gsync(int* ctr, int* prev) {
    __threadfence();
    __syncthreads();
    if (threadIdx.x == 0) {
        int r = atomicAdd(ctr, 1);
        if (prev && r == NBLK - 1) *prev = 0;
        while (*(volatile int*)ctr < NBLK) __nanosleep(32);
    }
    __syncthreads();
    __threadfence();
}

// ---------------------------------------------------------------------------
// build: hist -> scan -> scatter in ONE persistent kernel (3 barriers).
// VERBATIM R13 build (validated: 13.7 us build-side).
__global__ __launch_bounds__(256) void build_kernel(
    const float* __restrict__ coord,
    const int*   __restrict__ asym,
    const int*   __restrict__ a2t)
{
    __shared__ float s_c[768];
    __shared__ int s_w[8];
    __shared__ int s_off;

    int tid = threadIdx.x;
    int t   = blockIdx.x * 256 + tid;    // 0 .. NS*NA-1 (exactly grid size)
    int s   = t >> 13;
    int a   = t & (NA - 1);

    // ---- P1: coalesced coord stage, histogram (rank = atomic return) ------
    {
        const float* cb = coord + (size_t)blockIdx.x * 768;
        s_c[tid]       = cb[tid];
        s_c[tid + 256] = cb[tid + 256];
        s_c[tid + 512] = cb[tid + 512];
    }
    __syncthreads();
    float x = s_c[3 * tid], y = s_c[3 * tid + 1], z = s_c[3 * tid + 2];
    float q = fmaf(x, x, fmaf(y, y, z * z));
    int cell = cellco(x) + GRID * cellco(y) + GRIDXY * cellco(z);
    int rank = atomicAdd(&g_cellCounts[s][cell], 1);
    if (t < NA) {
        int ch = asym[a2t[t]];
        g_chain[t] = ch;
        atomicAdd(&g_npc[ch], 1);
    }

    gsync(&g_sync0, 0);

    // ---- P2a: local scan of this block's 1024-cell chunk ------------------
    int sb = blockIdx.x >> 5;
    int ch = blockIdx.x & 31;
    int base = ch * 1024 + tid * 4;
    int4 v = *(const int4*)(g_cellCounts[sb] + base);
    int sum = v.x + v.y + v.z + v.w;

    int lane = tid & 31, wid = tid >> 5;
    int inc = sum;
#pragma unroll
    for (int d = 1; d < 32; d <<= 1) {
        int u = __shfl_up_sync(0xFFFFFFFF, inc, d);
        if (lane >= d) inc += u;
    }
    if (lane == 31) s_w[wid] = inc;
    __syncthreads();
    if (tid < 8) {
        int wv = s_w[tid];
        int wi = wv;
#pragma unroll
        for (int d = 1; d < 8; d <<= 1) {
            int u = __shfl_up_sync(0xFF, wi, d);
            if (tid >= d) wi += u;
        }
        s_w[tid] = wi - wv;
        if (tid == 7) g_partial[sb * 32 + ch] = wi;
    }
    __syncthreads();
    int run = s_w[wid] + (inc - sum);
    *(int4*)(g_cellCounts[sb] + base) = make_int4(0, 0, 0, 0);

    gsync(&g_sync1, &g_sync0);

    // ---- P2b: add cross-chunk offset, store starts -------------------------
    if (tid < 32) {
        int pv = (tid < ch) ? g_partial[sb * 32 + tid] : 0;
#pragma unroll
        for (int d = 16; d > 0; d >>= 1)
            pv += __shfl_down_sync(0xFFFFFFFF, pv, d);
        if (tid == 0) s_off = pv;
    }
    __syncthreads();
    int off = s_off;
    int4 o;
    o.x = run + off;
    o.y = o.x + v.x;
    o.z = o.y + v.y;
    o.w = o.z + v.z;
    *(int4*)(g_cellStarts[sb] + base) = o;
    if (ch == 31 && tid == 255) g_cellStarts[sb][CELLS] = NA;

    gsync(&g_sync2, &g_sync1);

    // ---- P3: scatter from registers ----------------------------------------
    int pos = g_cellStarts[s][cell] + rank;
    g_pk[s][pos]   = make_float4(x, y, z, q);
    g_meta[s][pos] = g_chain[a];
}

// ---------------------------------------------------------------------------
// search: VERBATIM R11 search (validated: 12.2 us). Forward half-stencil,
// thread per (atom, segment). Segments:
//    0..2: rows (z+1, y-1..y+1); 3: row (z, y+1); 4: own row tail j>k.
// Forward cells have larger linear index and the own-cell scan starts at k+1,
// so each unordered pair is visited exactly once with no id test. fp32
// predicate association identical to the accepted brute-force kernel.
// Last-arriving block runs the fused finalize and resets replay counters.
// out layout: [ has (256 floats) | details (512 floats, (tot, rel)) ]
__global__ __launch_bounds__(256, 8) void search_kernel(float* __restrict__ out) {
    __shared__ int scnt[NC * NC];
    __shared__ int s_last;
    int tid = threadIdx.x;
    if (tid < NC * NC) scnt[tid] = 0;
    __syncthreads();

    int bx  = blockIdx.x;
    int seg = bx >> 7;                     // 0..4
    int t   = ((bx & 127) << 8) | tid;
    int s   = t >> 13;
    int k   = t & (NA - 1);

    float4 p  = g_pk[s][k];
    int    ci = g_meta[s][k];

    float m2x = -2.0f * p.x, m2y = -2.0f * p.y, m2z = -2.0f * p.z;
    float K   = p.w - THR2;

    int cx = cellco(p.x), cy = cellco(p.y), cz = cellco(p.z);
    int x0 = max(cx - 1, 0), x1 = min(cx + 1, GRID - 1);

    const int* st = g_cellStarts[s];
    int lo = 0, hi = 0;
    if (seg < 3) {
        int zz = cz + 1, yy = cy - 1 + seg;
        if (zz < GRID && yy >= 0 && yy < GRID) {
            int row = GRID * yy + GRIDXY * zz;
            lo = st[row + x0];
            hi = st[row + x1 + 1];
        }
    } else if (seg == 3) {
        int yy = cy + 1;
        if (yy < GRID) {
            int row = GRID * yy + GRIDXY * cz;
            lo = st[row + x0];
            hi = st[row + x1 + 1];
        }
    } else {
        int row = GRID * cy + GRIDXY * cz;
        lo = k + 1;                        // own-cell tail + forward-x cell
        hi = st[row + x1 + 1];
    }

    const float4* pk = g_pk[s];
    const int*    mt = g_meta[s];
    int bucket = ci * NC;

    int j = lo;
    for (; j + 1 < hi; j += 2) {
        float4 a = pk[j];
        float4 c = pk[j + 1];
        int ma = mt[j];
        int mb = mt[j + 1];
        float da = fmaf(m2z, a.z, fmaf(m2y, a.y, fmaf(m2x, a.x, a.w))) + K;
        float db = fmaf(m2z, c.z, fmaf(m2y, c.y, fmaf(m2x, c.x, c.w))) + K;
        if (da < 0.0f && ma != ci) atomicAdd(&scnt[bucket + ma], 1);
        if (db < 0.0f && mb != ci) atomicAdd(&scnt[bucket + mb], 1);
    }
    if (j < hi) {
        float4 a = pk[j];
        int ma = mt[j];
        float da = fmaf(m2z, a.z, fmaf(m2y, a.y, fmaf(m2x, a.x, a.w))) + K;
        if (da < 0.0f && ma != ci) atomicAdd(&scnt[bucket + ma], 1);
    }

    __syncthreads();
    if (tid < NC * NC) {
        int v = scnt[tid];
        if (v) atomicAdd(&g_counts[s * NC * NC + tid], v);
    }
    __threadfence();
    __syncthreads();
    if (tid == 0) {
        int r = atomicAdd(&g_sd, 1);
        s_last = (r == SBLK - 1);
        if (s_last) { g_sd = 0; g_sync2 = 0; }   // reset replay counters
    }
    __syncthreads();
    if (!s_last) return;

    // ---- fused finalize (256 threads -> one (sample, a, b) each) ----
    {
        int fs = tid >> 6;
        int r  = tid & 63;
        int a  = r >> 3;
        int b  = r & 7;

        int tot_i = 0;
        if (a != b)
            tot_i = __ldcg(&g_counts[fs * NC * NC + a * NC + b]) +
                    __ldcg(&g_counts[fs * NC * NC + b * NC + a]);
        float tot = (float)tot_i;
        float mn  = (float)min(__ldcg(&g_npc[a]), __ldcg(&g_npc[b]));
        float rel = tot / mn;
        bool  has = (tot > 100.0f) || (rel > 0.5f);

        out[tid]                        = has ? 1.0f : 0.0f;
        out[NS * NC * NC + 2 * tid]     = tot;
        out[NS * NC * NC + 2 * tid + 1] = rel;

        __syncthreads();                   // all reads done
        g_counts[tid] = 0;                 // reset replay invariants
        if (tid < NC) g_npc[tid] = 0;
    }
}

// ---------------------------------------------------------------------------
extern "C" void kernel_launch(void* const* d_in, const int* in_sizes, int n_in,
                              void* d_out, int out_size) {
    const float* coord = (const float*)d_in[0];   // [S, N, 3] f32
    const int*   asym  = (const int*)  d_in[1];   // [N_TOKENS] i32
    const int*   a2t   = (const int*)  d_in[2];   // [N] i32
    float*       out   = (float*)d_out;

    build_kernel <<<NBLK, 256>>>(coord, asym, a2t);
    search_kernel<<<SBLK, 256>>>(out);
}